// round 1
// baseline (speedup 1.0000x reference)
#include <cuda_runtime.h>

// Problem dims (fixed by the dataset)
#define ZD 96
#define YD 96
#define XD 96
#define PL (YD * XD)          // 9216   (one z-plane)
#define VOL (ZD * YD * XD)    // 884736
#define CH 4
#define HS 3
#define KW 7

// ---------------- persistent device scratch ----------------
__device__ float g_wlif[CH][KW];    // normalized 1D gaussian (sigma3)
__device__ float g_wq[CH][KW];      // normalized 1D gaussian (sigma2)
__device__ float g_slif[CH][ZD];    // boundary partial sums of g_wlif (conv_ones factor)
__device__ float g_u[CH * VOL];     // current u                (14.2 MB)
__device__ float g_bufA[12 * VOL];  // stream buffer A          (42.5 MB)
__device__ float g_bufB[12 * VOL];  // stream buffer B          (42.5 MB)

// ---------------- setup: weights + boundary sums ----------------
__global__ void k_setup(const float* __restrict__ sigma2,
                        const float* __restrict__ sigma3) {
    int c = threadIdx.x;
    if (c < CH) {
        float s2 = sigma2[c], s3 = sigma3[c];
        float w2[KW], w3[KW];
        float sum2 = 0.f, sum3 = 0.f;
        for (int t = 0; t < KW; t++) {
            float d = (float)(t - HS);
            w2[t] = expf(-d * d / (2.f * s2 * s2)); sum2 += w2[t];
            w3[t] = expf(-d * d / (2.f * s3 * s3)); sum3 += w3[t];
        }
        for (int t = 0; t < KW; t++) {
            g_wq[c][t]  = w2[t] / sum2;
            g_wlif[c][t] = w3[t] / sum3;
        }
        for (int p = 0; p < ZD; p++) {
            float s = 0.f;
            for (int t = 0; t < KW; t++) {
                int q = p + t - HS;
                if (q >= 0 && q < ZD) s += g_wlif[c][t];
            }
            g_slif[c][p] = s;
        }
    }
}

// ---------------- u0 = softmax(o / eta) ----------------
__global__ void k_init(const float* __restrict__ o,
                       const float* __restrict__ eta_p) {
    int i = blockIdx.x * blockDim.x + threadIdx.x;
    if (i >= VOL) return;
    float inv_eta = 1.f / eta_p[0];
    float a0 = o[i] * inv_eta;
    float a1 = o[VOL + i] * inv_eta;
    float a2 = o[2 * VOL + i] * inv_eta;
    float a3 = o[3 * VOL + i] * inv_eta;
    float m = fmaxf(fmaxf(a0, a1), fmaxf(a2, a3));
    float e0 = expf(a0 - m), e1 = expf(a1 - m), e2 = expf(a2 - m), e3 = expf(a3 - m);
    float inv = 1.f / (e0 + e1 + e2 + e3);
    g_u[i] = e0 * inv;
    g_u[VOL + i] = e1 * inv;
    g_u[2 * VOL + i] = e2 * inv;
    g_u[3 * VOL + i] = e3 * inv;
}

// ---------------- stage 1: z-conv of {u*I, u, 1-2u} (per channel) ----------------
// writes bufA virtual channels: [0..3]=uI(z), [4..7]=u(z), [8..11]=w(z)
__global__ void k_convz3(const float* __restrict__ I) {
    int i = blockIdx.x * blockDim.x + threadIdx.x;
    int c = blockIdx.y;
    if (i >= VOL) return;
    int z = i / PL;
    int r = i - z * PL;
    float auI = 0.f, au = 0.f, aw = 0.f;
#pragma unroll
    for (int t = 0; t < KW; t++) {
        int zz = z + t - HS;
        if (zz >= 0 && zz < ZD) {
            float uv = g_u[c * VOL + zz * PL + r];
            float Iv = I[zz * PL + r];
            float wl = g_wlif[c][t];
            float wq = g_wq[c][t];
            auI += wl * uv * Iv;
            au  += wl * uv;
            aw  += wq * (1.f - 2.f * uv);
        }
    }
    g_bufA[(0 * CH + c) * VOL + i] = auI;
    g_bufA[(1 * CH + c) * VOL + i] = au;
    g_bufA[(2 * CH + c) * VOL + i] = aw;
}

// ---------------- y-conv over 12 virtual channels: bufA -> bufB ----------------
__global__ void k_convy12() {
    int i = blockIdx.x * blockDim.x + threadIdx.x;
    int vc = blockIdx.y;  // 0..11
    if (i >= VOL) return;
    int z = i / PL;
    int r = i - z * PL;
    int y = r / XD;
    int x = r - y * XD;
    int c = vc & 3;
    const float* w = (vc < 8) ? g_wlif[c] : g_wq[c];
    const float* in = g_bufA + (long)vc * VOL;
    float acc = 0.f;
#pragma unroll
    for (int t = 0; t < KW; t++) {
        int yy = y + t - HS;
        if (yy >= 0 && yy < YD) acc += w[t] * in[z * PL + yy * XD + x];
    }
    g_bufB[(long)vc * VOL + i] = acc;
}

// ---------------- x-conv + Cn combine: bufB -> bufA ----------------
// out bufA: [0..3]=Cn, [4..7]=Cn^2, [8..11]=q
__global__ void k_convx_combine() {
    int i = blockIdx.x * blockDim.x + threadIdx.x;
    int c = blockIdx.y;
    if (i >= VOL) return;
    int x = i % XD;
    int base = i - x;
    float A = 0.f, B = 0.f, W = 0.f;
#pragma unroll
    for (int t = 0; t < KW; t++) {
        int xx = x + t - HS;
        if (xx >= 0 && xx < XD) {
            float wl = g_wlif[c][t];
            float wq = g_wq[c][t];
            A += wl * g_bufB[(0 * CH + c) * VOL + base + xx];
            B += wl * g_bufB[(1 * CH + c) * VOL + base + xx];
            W += wq * g_bufB[(2 * CH + c) * VOL + base + xx];
        }
    }
    float Cn = (A + 1e-6f) / (B + 1e-6f);
    g_bufA[(0 * CH + c) * VOL + i] = Cn;
    g_bufA[(1 * CH + c) * VOL + i] = Cn * Cn;
    g_bufA[(2 * CH + c) * VOL + i] = W;  // q
}

// ---------------- z-conv over 8 vch {Cn, Cn^2}: bufA -> bufB ----------------
__global__ void k_convz8() {
    int i = blockIdx.x * blockDim.x + threadIdx.x;
    int vc = blockIdx.y;  // 0..7
    if (i >= VOL) return;
    int z = i / PL;
    int r = i - z * PL;
    int c = vc & 3;
    const float* w = g_wlif[c];
    const float* in = g_bufA + (long)vc * VOL;
    float acc = 0.f;
#pragma unroll
    for (int t = 0; t < KW; t++) {
        int zz = z + t - HS;
        if (zz >= 0 && zz < ZD) acc += w[t] * in[zz * PL + r];
    }
    g_bufB[(long)vc * VOL + i] = acc;
}

// ---------------- y-conv over 8 vch: bufB -> bufA (q in [8..11] preserved) ----
__global__ void k_convy8() {
    int i = blockIdx.x * blockDim.x + threadIdx.x;
    int vc = blockIdx.y;  // 0..7
    if (i >= VOL) return;
    int z = i / PL;
    int r = i - z * PL;
    int y = r / XD;
    int x = r - y * XD;
    int c = vc & 3;
    const float* w = g_wlif[c];
    const float* in = g_bufB + (long)vc * VOL;
    float acc = 0.f;
#pragma unroll
    for (int t = 0; t < KW; t++) {
        int yy = y + t - HS;
        if (yy >= 0 && yy < YD) acc += w[t] * in[z * PL + yy * XD + x];
    }
    g_bufA[(long)vc * VOL + i] = acc;
}

// ---------------- final: x-conv of {Cn,Cn^2} + Lif + q + softmax ----------------
// if write_ext != 0 write to out, else write to g_u
__global__ void k_final(const float* __restrict__ o,
                        const float* __restrict__ I,
                        const float* __restrict__ eta_p,
                        const float* __restrict__ lam_p,
                        const float* __restrict__ mu_p,
                        float* out, int write_ext) {
    int i = blockIdx.x * blockDim.x + threadIdx.x;
    if (i >= VOL) return;
    int x = i % XD;
    int base = i - x;
    int z = i / PL;
    int r = i - z * PL;
    int y = r / XD;

    float Iv = I[i];
    float inv_eta = 1.f / eta_p[0];
    float lam = lam_p[0];
    float mu = mu_p[0];

    float a[CH];
#pragma unroll
    for (int c = 0; c < CH; c++) {
        float E = 0.f;  // conv(Cn)
        float D = 0.f;  // conv(Cn^2)
#pragma unroll
        for (int t = 0; t < KW; t++) {
            int xx = x + t - HS;
            if (xx >= 0 && xx < XD) {
                float wl = g_wlif[c][t];
                E += wl * g_bufA[(0 * CH + c) * VOL + base + xx];
                D += wl * g_bufA[(1 * CH + c) * VOL + base + xx];
            }
        }
        float q = g_bufA[(2 * CH + c) * VOL + i];
        float cones = g_slif[c][z] * g_slif[c][y] * g_slif[c][x];
        float Lif = D - 2.f * Iv * E + Iv * Iv * cones;
        a[c] = (o[c * VOL + i] - mu * Lif - lam * q) * inv_eta;
    }
    float m = fmaxf(fmaxf(a[0], a[1]), fmaxf(a[2], a[3]));
    float e0 = expf(a[0] - m), e1 = expf(a[1] - m);
    float e2 = expf(a[2] - m), e3 = expf(a[3] - m);
    float inv = 1.f / (e0 + e1 + e2 + e3);
    float* dst = write_ext ? out : g_u;
    dst[i] = e0 * inv;
    dst[VOL + i] = e1 * inv;
    dst[2 * VOL + i] = e2 * inv;
    dst[3 * VOL + i] = e3 * inv;
}

// ---------------- launch ----------------
extern "C" void kernel_launch(void* const* d_in, const int* in_sizes, int n_in,
                              void* d_out, int out_size) {
    const float* o      = (const float*)d_in[0];
    const float* I      = (const float*)d_in[1];
    const float* sigma2 = (const float*)d_in[2];
    const float* sigma3 = (const float*)d_in[3];
    const float* eta    = (const float*)d_in[4];
    const float* lam    = (const float*)d_in[5];
    const float* mu     = (const float*)d_in[6];
    float* out = (float*)d_out;

    const int T = 256;
    const int B = (VOL + T - 1) / T;  // 3456

    k_setup<<<1, 32>>>(sigma2, sigma3);
    k_init<<<B, T>>>(o, eta);

    const int NB_ITERS = 10;
    for (int it = 0; it < NB_ITERS; ++it) {
        k_convz3<<<dim3(B, CH), T>>>(I);
        k_convy12<<<dim3(B, 12), T>>>();
        k_convx_combine<<<dim3(B, CH), T>>>();
        k_convz8<<<dim3(B, 8), T>>>();
        k_convy8<<<dim3(B, 8), T>>>();
        k_final<<<B, T>>>(o, I, eta, lam, mu, out, (it == NB_ITERS - 1) ? 1 : 0);
    }
}